// round 14
// baseline (speedup 1.0000x reference)
#include <cuda_runtime.h>
#include <cooperative_groups.h>
#include <stdint.h>

namespace cg = cooperative_groups;

// Problem constants (fixed shapes for this problem instance)
#define NB    16
#define HWPIX (512 * 512)          // pixels per image
#define NPIX  (NB * HWPIX)         // total pixels
#define WPI   8192                 // 32-bit words per bitpacked image (512 rows * 16 words)
#define SMOOTHV 1e-6
#define CSIZE 4                    // CTAs per image (cluster size)
#define WPC   (WPI / CSIZE)        // 2048 words per CTA
#define RPC   128                  // rows per CTA

// Scratch: bitpacked binarized images / skeletons
__device__ uint32_t g_pbits[NB * WPI];
__device__ uint32_t g_tbits[NB * WPI];

// Reduction state, zeroed by one cudaMemsetAsync per launch.
// acc: [0]=I1 (sum p1 over true) [1]=S1 (sum p1) [2]=F (focal sum)
// c1: count of true pixels; cnt: per image {inter(unused), sum_p, sum_t}
// imgtick: per-image CTA-completion tickets (8 each); gtick: final election
struct Red {
    double acc[3];
    double dratio;
    int    c1;
    int    cnt[NB * 3];
    int    imgtick[NB];
    unsigned int gtick;
};
__device__ Red g_red;

// ---------------------------------------------------------------------------
// Kernel 1: softmax + focal + dice partials + bitpacked binarization.
// 8 pixels per thread (2x float4 per plane + 2x int4); words assembled from
// bytes with 2 shfl_xor OR-steps per 4-lane group.
// ---------------------------------------------------------------------------
__global__ __launch_bounds__(1024) void k_pixel(const float* __restrict__ logits_,
                                                const int* __restrict__ truth_) {
    const float4* __restrict__ logits = (const float4*)logits_;
    const int4*   __restrict__ truth  = (const int4*)truth_;
    const int tid  = threadIdx.x;
    const int idx8 = blockIdx.x * 1024 + tid;   // byte-group index (8 px), 0..524287
    const int b    = idx8 >> 15;                // 32768 groups per image
    const int i8   = idx8 & 32767;
    const int qb   = b * 131072 + i8 * 2;       // quad index in logits planes

    const float4 l0a = logits[qb];
    const float4 l0b = logits[qb + 1];
    const float4 l1a = logits[qb + 65536];
    const float4 l1b = logits[qb + 65536 + 1];
    const int4   ta  = truth[idx8 * 2];
    const int4   tb4 = truth[idx8 * 2 + 1];

    float L0[8] = {l0a.x, l0a.y, l0a.z, l0a.w, l0b.x, l0b.y, l0b.z, l0b.w};
    float L1[8] = {l1a.x, l1a.y, l1a.z, l1a.w, l1b.x, l1b.y, l1b.z, l1b.w};
    int   TV[8] = {ta.x, ta.y, ta.z, ta.w, tb4.x, tb4.y, tb4.z, tb4.w};

    float aI1 = 0.f, aS1 = 0.f, aF = 0.f;
    uint32_t pbyte = 0u, tbyte = 0u;

#pragma unroll
    for (int j = 0; j < 8; ++j) {
        float d  = L0[j] - L1[j];
        float ad = fabsf(d);
        float u  = __expf(-ad);
        float pmax = 1.0f / (1.0f + u);
        bool  pb = (d < 0.0f);
        bool  tb = (TV[j] > 0);
        float p1 = pb ? pmax : (1.0f - pmax);
        float lg = __logf(1.0f + u);
        float ce = (pb == tb) ? lg : (ad + lg);  // -log p_true
        float pt = tb ? p1 : (1.0f - p1);
        float om = 1.0f - pt;
        aF += 0.25f * om * om * ce;
        if (tb) aI1 += p1;
        aS1 += p1;
        pbyte |= (pb ? 1u : 0u) << j;
        tbyte |= (tb ? 1u : 0u) << j;
    }
    int aC1 = __popc(tbyte);

    // assemble 32-pixel words across groups of 4 lanes (byte position idx8&3)
    uint32_t pw = pbyte << ((idx8 & 3) * 8);
    uint32_t tw = tbyte << ((idx8 & 3) * 8);
#pragma unroll
    for (int off = 1; off < 4; off <<= 1) {
        pw |= __shfl_xor_sync(0xffffffffu, pw, off);
        tw |= __shfl_xor_sync(0xffffffffu, tw, off);
    }
    if ((idx8 & 3) == 0) {
        g_pbits[idx8 >> 2] = pw;
        g_tbits[idx8 >> 2] = tw;
    }

    // block reduction -> 3 double atomics + 1 int atomic per block
    __shared__ float redf[32][3];
    __shared__ int   redi[32];
    const int lane = tid & 31, warp = tid >> 5;
#pragma unroll
    for (int off = 16; off; off >>= 1) {
        aI1 += __shfl_down_sync(0xffffffffu, aI1, off);
        aS1 += __shfl_down_sync(0xffffffffu, aS1, off);
        aF  += __shfl_down_sync(0xffffffffu, aF , off);
        aC1 += __shfl_down_sync(0xffffffffu, aC1, off);
    }
    if (lane == 0) {
        redf[warp][0] = aI1; redf[warp][1] = aS1; redf[warp][2] = aF;
        redi[warp] = aC1;
    }
    __syncthreads();
    if (warp == 0) {
        float v0 = redf[lane][0], v1 = redf[lane][1], v2 = redf[lane][2];
        int   v3 = redi[lane];
#pragma unroll
        for (int off = 16; off; off >>= 1) {
            v0 += __shfl_down_sync(0xffffffffu, v0, off);
            v1 += __shfl_down_sync(0xffffffffu, v1, off);
            v2 += __shfl_down_sync(0xffffffffu, v2, off);
            v3 += __shfl_down_sync(0xffffffffu, v3, off);
        }
        if (lane == 0) {
            atomicAdd(&g_red.acc[0], (double)v0);
            atomicAdd(&g_red.acc[1], (double)v1);
            atomicAdd(&g_red.acc[2], (double)v2);
            atomicAdd(&g_red.c1, v3);
        }
    }
}

// ---------------------------------------------------------------------------
// Kernel 2: Zhang-Suen skeletonization, 4-CTA cluster per image, bit-parallel,
// double-buffered, word-level change masks, parity-flag convergence
// (exactly 2 cluster.syncs per iteration).  [R8/R13 known-good protocol]
// Tail: per-image ticket -> 8th CTA computes intersection + clDice ratio;
// global ticket -> 16th elected CTA performs the final scalar combine.
// ---------------------------------------------------------------------------
__device__ __forceinline__ void fadd(uint32_t a, uint32_t b, uint32_t c,
                                     uint32_t& s, uint32_t& cy) {
    uint32_t x = a ^ b; s = x ^ c; cy = (a & b) | (x & c);
}
__device__ __forceinline__ void hadd(uint32_t a, uint32_t b,
                                     uint32_t& s, uint32_t& cy) {
    s = a ^ b; cy = a & b;
}

template <int SUB>
__device__ __forceinline__ uint32_t thin_word(const uint32_t* img, int idx, int c) {
    uint32_t cur = img[idx];
    if (!cur) return 0u;
    bool cL = c > 0, cR = c < 15;
    uint32_t up = img[idx - 16];
    uint32_t dn = img[idx + 16];
    uint32_t lf = cL ? img[idx - 1]  : 0u;
    uint32_t rt = cR ? img[idx + 1]  : 0u;
    uint32_t ul = cL ? img[idx - 17] : 0u;
    uint32_t ur = cR ? img[idx - 15] : 0u;
    uint32_t dl = cL ? img[idx + 15] : 0u;
    uint32_t dr = cR ? img[idx + 17] : 0u;

    uint32_t p2 = up;                                 // N
    uint32_t p3 = (up >> 1) | (ur << 31);             // NE
    uint32_t p4 = (cur >> 1) | (rt << 31);            // E
    uint32_t p5 = (dn >> 1) | (dr << 31);             // SE
    uint32_t p6 = dn;                                 // S
    uint32_t p7 = (dn << 1) | (dl >> 31);             // SW
    uint32_t p8 = (cur << 1) | (lf >> 31);            // W
    uint32_t p9 = (up << 1) | (ul >> 31);             // NW

    uint32_t s1, c1, s2, c2, s3, c3, S0, c4, s5, c5, S1, c6, S2, S3;
    fadd(p2, p3, p4, s1, c1);
    fadd(p5, p6, p7, s2, c2);
    hadd(p8, p9, s3, c3);
    fadd(s1, s2, s3, S0, c4);
    fadd(c1, c2, c3, s5, c5);
    hadd(s5, c4, S1, c6);
    hadd(c5, c6, S2, S3);
    uint32_t ge2 = S1 | S2 | S3;
    uint32_t le6 = ~(S3 | (S2 & S1 & S0));

    uint32_t t0 = ~p2 & p3, t1 = ~p3 & p4, t2 = ~p4 & p5, t3 = ~p5 & p6;
    uint32_t t4 = ~p6 & p7, t5 = ~p7 & p8, t6 = ~p8 & p9, t7 = ~p9 & p2;
    uint32_t a1, d1, a2, d2, a3, d3, A0, d4, a5, d5, A1, d6, A2, A3;
    fadd(t0, t1, t2, a1, d1);
    fadd(t3, t4, t5, a2, d2);
    hadd(t6, t7, a3, d3);
    fadd(a1, a2, a3, A0, d4);
    fadd(d1, d2, d3, a5, d5);
    hadd(a5, d4, A1, d6);
    hadd(d5, d6, A2, A3);
    uint32_t aeq1 = A0 & ~(A1 | A2 | A3);

    uint32_t cond34;
    if (SUB == 0)
        cond34 = ~(p4 & p6 & (p2 | p8));
    else
        cond34 = ~(p2 & p8 & (p4 | p6));

    uint32_t remove = cur & ge2 & le6 & aeq1 & cond34;
    return cur & ~remove;
}

#define BWORDS ((RPC + 2) * 16)   // 2080 words per buffer (halo rows 0 and 129)
#define CROWS  (RPC + 2)

__global__ __launch_bounds__(1024) __cluster_dims__(CSIZE, 1, 1)
void k_skel(float* __restrict__ out) {
    __shared__ uint32_t buf[2][BWORDS];   // ping-pong image buffers
    __shared__ uint32_t chg[3][CROWS];    // per-row 16-bit word-change masks, 3 rotating slots
    __shared__ uint32_t rc[CROWS];        // combined masks (last two sub-passes)
    __shared__ int s_flag[2];             // parity-indexed convergence flags
    __shared__ int s_rem[CSIZE];

    const int tid = threadIdx.x;
    cg::cluster_group cluster = cg::this_cluster();
    const unsigned rank = cluster.block_rank();
    const unsigned image = blockIdx.x / CSIZE;

    uint32_t* src = (image < NB) ? &g_pbits[image * WPI]
                                 : &g_tbits[(image - NB) * WPI];
    uint32_t* my = src + rank * WPC;

    const bool hasUp = (rank > 0), hasDn = (rank + 1 < CSIZE);
    uint32_t* pu_buf = hasUp ? (uint32_t*)cluster.map_shared_rank((void*)buf, rank - 1) : nullptr;
    uint32_t* pd_buf = hasDn ? (uint32_t*)cluster.map_shared_rank((void*)buf, rank + 1) : nullptr;
    volatile uint32_t* pu_chg = hasUp ? (volatile uint32_t*)cluster.map_shared_rank((void*)chg, rank - 1) : nullptr;
    volatile uint32_t* pd_chg = hasDn ? (volatile uint32_t*)cluster.map_shared_rank((void*)chg, rank + 1) : nullptr;

    // load own 128 rows into buf[0] rows 1..128
#pragma unroll
    for (int k = 0; k < 2; ++k) {
        int w = tid + k * 1024;
        buf[0][16 + w] = my[w];
    }
    if (tid < CROWS) { chg[1][tid] = 0xFFFFu; chg[2][tid] = 0xFFFFu; }
    if (tid < 2) s_flag[tid] = 0;
    cluster.sync();

    int p = 0;                   // current buffer parity (returns to 0 each iter)
    int tw = 0, t1 = 1, t2 = 2;  // chg slots: write / last pass / pass before

    for (int iter = 0; iter < 512; ++iter) {
        const int q = iter & 1;
        // Reset slot q. Peers last read it at the end of iteration iter-2;
        // two cluster.syncs (iteration iter-1) have passed since -> safe.
        if (tid == 0) s_flag[q] = 0;
        int changed = 0;

#pragma unroll
        for (int sub = 0; sub < 2; ++sub) {
            uint32_t* cur = buf[p];
            uint32_t* nxt = buf[p ^ 1];

            // halo copy + combined word-change masks (slots t1|t2)
            if (tid < 16) {
                cur[tid] = hasUp ? pu_buf[p * BWORDS + RPC * 16 + tid] : 0u;
            } else if (tid < 32) {
                cur[(RPC + 1) * 16 + (tid - 16)] =
                    hasDn ? pd_buf[p * BWORDS + 16 + (tid - 16)] : 0u;
            } else if (tid < 32 + CROWS) {
                int r = tid - 32;
                uint32_t v;
                if (r == 0)
                    v = hasUp ? (pu_chg[t1 * CROWS + RPC] |
                                 pu_chg[t2 * CROWS + RPC]) : 0u;
                else if (r == RPC + 1)
                    v = hasDn ? (pd_chg[t1 * CROWS + 1] |
                                 pd_chg[t2 * CROWS + 1]) : 0u;
                else
                    v = chg[t1][r] | chg[t2][r];
                rc[r] = v;
            }
            __syncthreads();

#pragma unroll
            for (int k = 0; k < 2; ++k) {
                int w = tid + k * 1024;
                int r = (w >> 4) + 1;
                int c = w & 15;
                int idx = 16 + w;
                uint32_t o = cur[idx];
                // word (r,c) active iff any of 9 neighbor words changed in
                // the last two sub-passes
                uint32_t nb = rc[r - 1] | rc[r] | rc[r + 1];
                nb |= (nb << 1) | (nb >> 1);
                uint32_t n = o;
                if ((nb >> c) & 1u)
                    n = (sub == 0) ? thin_word<0>(cur, idx, c)
                                   : thin_word<1>(cur, idx, c);
                nxt[idx] = n;
                unsigned bm = __ballot_sync(0xffffffffu, n != o);
                changed |= (bm != 0u);
                int ln = tid & 31;
                if (ln == 0)       chg[tw][r] = bm & 0xFFFFu;   // low half-warp row
                else if (ln == 16) chg[tw][r] = bm >> 16;       // high half-warp row
            }
            if (sub == 1 && changed) s_flag[q] = 1;
            cluster.sync();

            p ^= 1;
            int tmp = t2; t2 = t1; t1 = tw; tw = tmp;
        }

        // convergence: peers' flags for this iteration are visible after the
        // sub==1 cluster.sync above. No extra cluster.sync needed.
        if (tid < CSIZE)
            s_rem[tid] = *(volatile int*)cluster.map_shared_rank((void*)&s_flag[q], tid);
        __syncthreads();
        if (!(s_rem[0] | s_rem[1] | s_rem[2] | s_rem[3])) break;
    }

    // ---- store result + per-CTA popcounts for clDice (sum_p / sum_t) ----
    const int img16 = (image < NB) ? (int)image : (int)(image - NB);
    int pcnt = 0;
#pragma unroll
    for (int k = 0; k < 2; ++k) {
        int w = tid + k * 1024;
        uint32_t v = buf[p][16 + w];
        my[w] = v;
        pcnt += __popc(v);
    }
#pragma unroll
    for (int off = 16; off; off >>= 1)
        pcnt += __shfl_down_sync(0xffffffffu, pcnt, off);
    __shared__ int sred[32];
    __shared__ int s_elect;
    if ((tid & 31) == 0) sred[tid >> 5] = pcnt;
    __syncthreads();
    if (tid < 32) {
        int v = sred[tid];
#pragma unroll
        for (int off = 16; off; off >>= 1)
            v += __shfl_down_sync(0xffffffffu, v, off);
        if (tid == 0) {
            int slot = (image < NB) ? 1 : 2;  // sum_p or sum_t
            atomicAdd(&g_red.cnt[img16 * 3 + slot], v);
            __threadfence();                   // bits + counts visible first
            int t = atomicAdd(&g_red.imgtick[img16], 1);
            s_elect = (t == 2 * CSIZE - 1);    // 8th (last) CTA for this image
        }
    }
    __syncthreads();
    if (!s_elect) return;

    // ---- elected CTA: intersection popcount + clDice ratio for this image ----
    const uint4* pa = (const uint4*)&g_pbits[img16 * WPI];
    const uint4* pb = (const uint4*)&g_tbits[img16 * WPI];
    int li = 0;
#pragma unroll
    for (int k = 0; k < 2; ++k) {
        int i4 = tid + k * 1024;
        uint4 a = pa[i4], b = pb[i4];
        li += __popc(a.x & b.x) + __popc(a.y & b.y) +
              __popc(a.z & b.z) + __popc(a.w & b.w);
    }
#pragma unroll
    for (int off = 16; off; off >>= 1)
        li += __shfl_down_sync(0xffffffffu, li, off);
    if ((tid & 31) == 0) sred[tid >> 5] = li;
    __syncthreads();
    if (tid != 0) return;
    {
        int I = 0;
#pragma unroll
        for (int j = 0; j < 32; ++j) I += sred[j];
        double P = (double)g_red.cnt[img16 * 3 + 1];
        double T = (double)g_red.cnt[img16 * 3 + 2];
        double ratio = (2.0 * (double)I + SMOOTHV) / (P + T + SMOOTHV);
        atomicAdd(&g_red.dratio, ratio);
        __threadfence();
        unsigned g = atomicAdd(&g_red.gtick, 1u);
        if (g == NB - 1) {
            // ---- final scalar combine (all ratios summed, acc from k_pixel) ----
            double I1 = g_red.acc[0], S1 = g_red.acc[1], F = g_red.acc[2];
            double C1 = (double)g_red.c1;
            double C0 = (double)NPIX - C1;
            double S0 = (double)NPIX - S1;
            double I0 = C0 - (S1 - I1);
            double dice = 1.0 - 0.5 * ((2.0 * I0 + SMOOTHV) / (S0 + C0 + SMOOTHV) +
                                       (2.0 * I1 + SMOOTHV) / (S1 + C1 + SMOOTHV));
            double focal = F / (double)NPIX;
            double cl = 1.0 - g_red.dratio / (double)NB;
            out[0] = (float)(0.7 * cl + 0.1 * dice + 0.2 * focal);
        }
    }
}

extern "C" void kernel_launch(void* const* d_in, const int* in_sizes, int n_in,
                              void* d_out, int out_size) {
    const float* logits = (const float*)d_in[0];   // [16,2,512,512] f32
    const int*   truth  = (const int*)d_in[1];     // [16,512,512] i32
    float* out = (float*)d_out;

    void* redp = nullptr;
    cudaGetSymbolAddress(&redp, g_red);
    cudaMemsetAsync(redp, 0, sizeof(Red), 0);

    k_pixel<<<512, 1024>>>(logits, truth);
    k_skel<<<NB * 2 * CSIZE, 1024>>>(out);
}

// round 15
// speedup vs baseline: 1.1023x; 1.1023x over previous
#include <cuda_runtime.h>
#include <cooperative_groups.h>
#include <stdint.h>

namespace cg = cooperative_groups;

// Problem constants (fixed shapes for this problem instance)
#define NB    16
#define HWPIX (512 * 512)          // pixels per image
#define NPIX  (NB * HWPIX)         // total pixels
#define WPI   8192                 // 32-bit words per bitpacked image (512 rows * 16 words)
#define SMOOTHV 1e-6
#define CSIZE 8                    // CTAs per image (cluster size)
#define WPC   (WPI / CSIZE)        // 1024 words per CTA
#define RPC   64                   // rows per CTA
#define SKTHREADS 512              // threads per skel CTA (2 words/thread)

// Scratch: bitpacked binarized images / skeletons
__device__ uint32_t g_pbits[NB * WPI];
__device__ uint32_t g_tbits[NB * WPI];

// Reduction state, zeroed by one cudaMemsetAsync per launch.
struct Red {
    double acc[3];        // [0]=I1 (sum p1 over true) [1]=S1 (sum p1) [2]=F (focal)
    double dratio;        // sum of per-image clDice ratios
    int    c1;            // count of true pixels
    int    cnt[NB * 3];   // per image {unused, sum_p, sum_t}
    int    imgtick[NB];   // per-image CTA completion tickets (16 each)
    unsigned int gtick;   // final combine election
};
__device__ Red g_red;

// ---------------------------------------------------------------------------
// Kernel 1: softmax + focal + dice partials + bitpacked binarization.
// 8 pixels per thread (2x float4 per plane + 2x int4); words assembled from
// bytes with 2 shfl_xor OR-steps per 4-lane group.
// ---------------------------------------------------------------------------
__global__ __launch_bounds__(1024) void k_pixel(const float* __restrict__ logits_,
                                                const int* __restrict__ truth_) {
    const float4* __restrict__ logits = (const float4*)logits_;
    const int4*   __restrict__ truth  = (const int4*)truth_;
    const int tid  = threadIdx.x;
    const int idx8 = blockIdx.x * 1024 + tid;   // byte-group index (8 px)
    const int b    = idx8 >> 15;                // 32768 groups per image
    const int i8   = idx8 & 32767;
    const int qb   = b * 131072 + i8 * 2;       // quad index in logits planes

    const float4 l0a = logits[qb];
    const float4 l0b = logits[qb + 1];
    const float4 l1a = logits[qb + 65536];
    const float4 l1b = logits[qb + 65536 + 1];
    const int4   ta  = truth[idx8 * 2];
    const int4   tb4 = truth[idx8 * 2 + 1];

    float L0[8] = {l0a.x, l0a.y, l0a.z, l0a.w, l0b.x, l0b.y, l0b.z, l0b.w};
    float L1[8] = {l1a.x, l1a.y, l1a.z, l1a.w, l1b.x, l1b.y, l1b.z, l1b.w};
    int   TV[8] = {ta.x, ta.y, ta.z, ta.w, tb4.x, tb4.y, tb4.z, tb4.w};

    float aI1 = 0.f, aS1 = 0.f, aF = 0.f;
    uint32_t pbyte = 0u, tbyte = 0u;

#pragma unroll
    for (int j = 0; j < 8; ++j) {
        float d  = L0[j] - L1[j];
        float ad = fabsf(d);
        float u  = __expf(-ad);
        float pmax = 1.0f / (1.0f + u);
        bool  pb = (d < 0.0f);
        bool  tb = (TV[j] > 0);
        float p1 = pb ? pmax : (1.0f - pmax);
        float lg = __logf(1.0f + u);
        float ce = (pb == tb) ? lg : (ad + lg);  // -log p_true
        float pt = tb ? p1 : (1.0f - p1);
        float om = 1.0f - pt;
        aF += 0.25f * om * om * ce;
        if (tb) aI1 += p1;
        aS1 += p1;
        pbyte |= (pb ? 1u : 0u) << j;
        tbyte |= (tb ? 1u : 0u) << j;
    }
    int aC1 = __popc(tbyte);

    // assemble 32-pixel words across groups of 4 lanes (byte position idx8&3)
    uint32_t pw = pbyte << ((idx8 & 3) * 8);
    uint32_t tw = tbyte << ((idx8 & 3) * 8);
#pragma unroll
    for (int off = 1; off < 4; off <<= 1) {
        pw |= __shfl_xor_sync(0xffffffffu, pw, off);
        tw |= __shfl_xor_sync(0xffffffffu, tw, off);
    }
    if ((idx8 & 3) == 0) {
        g_pbits[idx8 >> 2] = pw;
        g_tbits[idx8 >> 2] = tw;
    }

    // block reduction -> 3 double atomics + 1 int atomic per block
    __shared__ float redf[32][3];
    __shared__ int   redi[32];
    const int lane = tid & 31, warp = tid >> 5;
#pragma unroll
    for (int off = 16; off; off >>= 1) {
        aI1 += __shfl_down_sync(0xffffffffu, aI1, off);
        aS1 += __shfl_down_sync(0xffffffffu, aS1, off);
        aF  += __shfl_down_sync(0xffffffffu, aF , off);
        aC1 += __shfl_down_sync(0xffffffffu, aC1, off);
    }
    if (lane == 0) {
        redf[warp][0] = aI1; redf[warp][1] = aS1; redf[warp][2] = aF;
        redi[warp] = aC1;
    }
    __syncthreads();
    if (warp == 0) {
        float v0 = redf[lane][0], v1 = redf[lane][1], v2 = redf[lane][2];
        int   v3 = redi[lane];
#pragma unroll
        for (int off = 16; off; off >>= 1) {
            v0 += __shfl_down_sync(0xffffffffu, v0, off);
            v1 += __shfl_down_sync(0xffffffffu, v1, off);
            v2 += __shfl_down_sync(0xffffffffu, v2, off);
            v3 += __shfl_down_sync(0xffffffffu, v3, off);
        }
        if (lane == 0) {
            atomicAdd(&g_red.acc[0], (double)v0);
            atomicAdd(&g_red.acc[1], (double)v1);
            atomicAdd(&g_red.acc[2], (double)v2);
            atomicAdd(&g_red.c1, v3);
        }
    }
}

// ---------------------------------------------------------------------------
// Kernel 2: Zhang-Suen skeletonization, 8-CTA cluster per image (64 rows,
// 512 threads per CTA -> 2 co-resident clusters per SM hide sync latency).
// Double-buffered, word-level change masks, parity-flag convergence
// (exactly 2 cluster.syncs per iteration). [R8/R13 known-good protocol]
// Tail: per-image ticket -> 16th CTA computes intersection + clDice ratio;
// global ticket -> elected CTA performs the final scalar combine.
// ---------------------------------------------------------------------------
__device__ __forceinline__ void fadd(uint32_t a, uint32_t b, uint32_t c,
                                     uint32_t& s, uint32_t& cy) {
    uint32_t x = a ^ b; s = x ^ c; cy = (a & b) | (x & c);
}
__device__ __forceinline__ void hadd(uint32_t a, uint32_t b,
                                     uint32_t& s, uint32_t& cy) {
    s = a ^ b; cy = a & b;
}

template <int SUB>
__device__ __forceinline__ uint32_t thin_word(const uint32_t* img, int idx, int c,
                                              uint32_t cur) {
    if (!cur) return 0u;
    bool cL = c > 0, cR = c < 15;
    uint32_t up = img[idx - 16];
    uint32_t dn = img[idx + 16];
    uint32_t lf = cL ? img[idx - 1]  : 0u;
    uint32_t rt = cR ? img[idx + 1]  : 0u;
    uint32_t ul = cL ? img[idx - 17] : 0u;
    uint32_t ur = cR ? img[idx - 15] : 0u;
    uint32_t dl = cL ? img[idx + 15] : 0u;
    uint32_t dr = cR ? img[idx + 17] : 0u;

    uint32_t p2 = up;                                  // N
    uint32_t p3 = __funnelshift_r(up, ur, 1);          // NE
    uint32_t p4 = __funnelshift_r(cur, rt, 1);         // E
    uint32_t p5 = __funnelshift_r(dn, dr, 1);          // SE
    uint32_t p6 = dn;                                  // S
    uint32_t p7 = __funnelshift_l(dl, dn, 1);          // SW
    uint32_t p8 = __funnelshift_l(lf, cur, 1);         // W
    uint32_t p9 = __funnelshift_l(ul, up, 1);          // NW

    uint32_t s1, c1, s2, c2, s3, c3, S0, c4, s5, c5, S1, c6, S2, S3;
    fadd(p2, p3, p4, s1, c1);
    fadd(p5, p6, p7, s2, c2);
    hadd(p8, p9, s3, c3);
    fadd(s1, s2, s3, S0, c4);
    fadd(c1, c2, c3, s5, c5);
    hadd(s5, c4, S1, c6);
    hadd(c5, c6, S2, S3);
    uint32_t ge2 = S1 | S2 | S3;
    uint32_t le6 = ~(S3 | (S2 & S1 & S0));

    uint32_t t0 = ~p2 & p3, t1 = ~p3 & p4, t2 = ~p4 & p5, t3 = ~p5 & p6;
    uint32_t t4 = ~p6 & p7, t5 = ~p7 & p8, t6 = ~p8 & p9, t7 = ~p9 & p2;
    uint32_t a1, d1, a2, d2, a3, d3, A0, d4, a5, d5, A1, d6, A2, A3;
    fadd(t0, t1, t2, a1, d1);
    fadd(t3, t4, t5, a2, d2);
    hadd(t6, t7, a3, d3);
    fadd(a1, a2, a3, A0, d4);
    fadd(d1, d2, d3, a5, d5);
    hadd(a5, d4, A1, d6);
    hadd(d5, d6, A2, A3);
    uint32_t aeq1 = A0 & ~(A1 | A2 | A3);

    uint32_t cond34;
    if (SUB == 0)
        cond34 = ~(p4 & p6 & (p2 | p8));
    else
        cond34 = ~(p2 & p8 & (p4 | p6));

    uint32_t remove = cur & ge2 & le6 & aeq1 & cond34;
    return cur & ~remove;
}

#define BWORDS ((RPC + 2) * 16)   // words per buffer (halo rows 0 and RPC+1)
#define CROWS  (RPC + 2)

__global__ __launch_bounds__(SKTHREADS) __cluster_dims__(CSIZE, 1, 1)
void k_skel(float* __restrict__ out) {
    __shared__ uint32_t buf[2][BWORDS];   // ping-pong image buffers
    __shared__ uint32_t chg[3][CROWS];    // per-row 16-bit word-change masks, 3 rotating slots
    __shared__ uint32_t rc[CROWS];        // combined masks (last two sub-passes)
    __shared__ int s_flag[2];             // parity-indexed convergence flags
    __shared__ int s_rem[CSIZE];

    const int tid = threadIdx.x;
    cg::cluster_group cluster = cg::this_cluster();
    const unsigned rank = cluster.block_rank();
    const unsigned image = blockIdx.x / CSIZE;

    uint32_t* src = (image < NB) ? &g_pbits[image * WPI]
                                 : &g_tbits[(image - NB) * WPI];
    uint32_t* my = src + rank * WPC;

    const bool hasUp = (rank > 0), hasDn = (rank + 1 < CSIZE);
    uint32_t* pu_buf = hasUp ? (uint32_t*)cluster.map_shared_rank((void*)buf, rank - 1) : nullptr;
    uint32_t* pd_buf = hasDn ? (uint32_t*)cluster.map_shared_rank((void*)buf, rank + 1) : nullptr;
    volatile uint32_t* pu_chg = hasUp ? (volatile uint32_t*)cluster.map_shared_rank((void*)chg, rank - 1) : nullptr;
    volatile uint32_t* pd_chg = hasDn ? (volatile uint32_t*)cluster.map_shared_rank((void*)chg, rank + 1) : nullptr;

    // load own rows into buf[0] rows 1..RPC
#pragma unroll
    for (int k = 0; k < 2; ++k) {
        int w = tid + k * SKTHREADS;
        buf[0][16 + w] = my[w];
    }
    if (tid < CROWS) { chg[1][tid] = 0xFFFFu; chg[2][tid] = 0xFFFFu; }
    if (tid < 2) s_flag[tid] = 0;
    cluster.sync();

    int p = 0;                   // current buffer parity (returns to 0 each iter)
    int tw = 0, t1 = 1, t2 = 2;  // chg slots: write / last pass / pass before

    for (int iter = 0; iter < 512; ++iter) {
        const int q = iter & 1;
        // Reset slot q. Peers last read it at the end of iteration iter-2;
        // two cluster.syncs (iteration iter-1) have passed since -> safe.
        if (tid == 0) s_flag[q] = 0;
        int changed = 0;

#pragma unroll
        for (int sub = 0; sub < 2; ++sub) {
            uint32_t* cur = buf[p];
            uint32_t* nxt = buf[p ^ 1];

            // halo copy + combined word-change masks (slots t1|t2)
            if (tid < 16) {
                cur[tid] = hasUp ? pu_buf[p * BWORDS + RPC * 16 + tid] : 0u;
            } else if (tid < 32) {
                cur[(RPC + 1) * 16 + (tid - 16)] =
                    hasDn ? pd_buf[p * BWORDS + 16 + (tid - 16)] : 0u;
            } else if (tid < 32 + CROWS) {
                int r = tid - 32;
                uint32_t v;
                if (r == 0)
                    v = hasUp ? (pu_chg[t1 * CROWS + RPC] |
                                 pu_chg[t2 * CROWS + RPC]) : 0u;
                else if (r == RPC + 1)
                    v = hasDn ? (pd_chg[t1 * CROWS + 1] |
                                 pd_chg[t2 * CROWS + 1]) : 0u;
                else
                    v = chg[t1][r] | chg[t2][r];
                rc[r] = v;
            }
            __syncthreads();

#pragma unroll
            for (int k = 0; k < 2; ++k) {
                int w = tid + k * SKTHREADS;
                int r = (w >> 4) + 1;
                int c = w & 15;
                int idx = 16 + w;
                uint32_t o = cur[idx];
                // word (r,c) active iff any of 9 neighbor words changed in
                // the last two sub-passes
                uint32_t nb = rc[r - 1] | rc[r] | rc[r + 1];
                nb |= (nb << 1) | (nb >> 1);
                uint32_t n = o;
                if ((nb >> c) & 1u)
                    n = (sub == 0) ? thin_word<0>(cur, idx, c, o)
                                   : thin_word<1>(cur, idx, c, o);
                nxt[idx] = n;
                unsigned bm = __ballot_sync(0xffffffffu, n != o);
                changed |= (bm != 0u);
                int ln = tid & 31;
                if (ln == 0)       chg[tw][r] = bm & 0xFFFFu;   // low half-warp row
                else if (ln == 16) chg[tw][r] = bm >> 16;       // high half-warp row
            }
            if (sub == 1 && changed) s_flag[q] = 1;
            cluster.sync();

            p ^= 1;
            int tmp = t2; t2 = t1; t1 = tw; tw = tmp;
        }

        // convergence: peers' flags for this iteration are visible after the
        // sub==1 cluster.sync above. No extra cluster.sync needed.
        if (tid < CSIZE)
            s_rem[tid] = *(volatile int*)cluster.map_shared_rank((void*)&s_flag[q], tid);
        __syncthreads();
        int any = 0;
#pragma unroll
        for (int j = 0; j < CSIZE; ++j) any |= s_rem[j];
        if (!any) break;
    }

    // ---- store result + per-CTA popcounts for clDice (sum_p / sum_t) ----
    const int img16 = (image < NB) ? (int)image : (int)(image - NB);
    int pcnt = 0;
#pragma unroll
    for (int k = 0; k < 2; ++k) {
        int w = tid + k * SKTHREADS;
        uint32_t v = buf[p][16 + w];
        my[w] = v;
        pcnt += __popc(v);
    }
#pragma unroll
    for (int off = 16; off; off >>= 1)
        pcnt += __shfl_down_sync(0xffffffffu, pcnt, off);
    __shared__ int sred[SKTHREADS / 32];
    __shared__ int s_elect;
    if ((tid & 31) == 0) sred[tid >> 5] = pcnt;
    __syncthreads();
    if (tid == 0) {
        int v = 0;
#pragma unroll
        for (int j = 0; j < SKTHREADS / 32; ++j) v += sred[j];
        int slot = (image < NB) ? 1 : 2;  // sum_p or sum_t
        atomicAdd(&g_red.cnt[img16 * 3 + slot], v);
        __threadfence();                   // bits + counts visible first
        int t = atomicAdd(&g_red.imgtick[img16], 1);
        s_elect = (t == 2 * CSIZE - 1);    // 16th (last) CTA for this image
    }
    __syncthreads();
    if (!s_elect) return;

    // ---- elected CTA: intersection popcount + clDice ratio for this image ----
    const uint4* pa = (const uint4*)&g_pbits[img16 * WPI];
    const uint4* pb = (const uint4*)&g_tbits[img16 * WPI];
    int li = 0;
#pragma unroll
    for (int k = 0; k < 4; ++k) {
        int i4 = tid + k * SKTHREADS;
        uint4 a = pa[i4], b = pb[i4];
        li += __popc(a.x & b.x) + __popc(a.y & b.y) +
              __popc(a.z & b.z) + __popc(a.w & b.w);
    }
#pragma unroll
    for (int off = 16; off; off >>= 1)
        li += __shfl_down_sync(0xffffffffu, li, off);
    if ((tid & 31) == 0) sred[tid >> 5] = li;
    __syncthreads();
    if (tid != 0) return;
    {
        int I = 0;
#pragma unroll
        for (int j = 0; j < SKTHREADS / 32; ++j) I += sred[j];
        double P = (double)g_red.cnt[img16 * 3 + 1];
        double T = (double)g_red.cnt[img16 * 3 + 2];
        double ratio = (2.0 * (double)I + SMOOTHV) / (P + T + SMOOTHV);
        atomicAdd(&g_red.dratio, ratio);
        __threadfence();
        unsigned g = atomicAdd(&g_red.gtick, 1u);
        if (g == NB - 1) {
            // ---- final scalar combine ----
            double I1 = g_red.acc[0], S1 = g_red.acc[1], F = g_red.acc[2];
            double C1 = (double)g_red.c1;
            double C0 = (double)NPIX - C1;
            double S0 = (double)NPIX - S1;
            double I0 = C0 - (S1 - I1);
            double dice = 1.0 - 0.5 * ((2.0 * I0 + SMOOTHV) / (S0 + C0 + SMOOTHV) +
                                       (2.0 * I1 + SMOOTHV) / (S1 + C1 + SMOOTHV));
            double focal = F / (double)NPIX;
            double cl = 1.0 - g_red.dratio / (double)NB;
            out[0] = (float)(0.7 * cl + 0.1 * dice + 0.2 * focal);
        }
    }
}

extern "C" void kernel_launch(void* const* d_in, const int* in_sizes, int n_in,
                              void* d_out, int out_size) {
    const float* logits = (const float*)d_in[0];   // [16,2,512,512] f32
    const int*   truth  = (const int*)d_in[1];     // [16,512,512] i32
    float* out = (float*)d_out;

    void* redp = nullptr;
    cudaGetSymbolAddress(&redp, g_red);
    cudaMemsetAsync(redp, 0, sizeof(Red), 0);

    k_pixel<<<512, 1024>>>(logits, truth);
    k_skel<<<NB * 2 * CSIZE, SKTHREADS>>>(out);
}